// round 2
// baseline (speedup 1.0000x reference)
#include <cuda_runtime.h>
#include <math.h>

// Problem constants
#define BB  2
#define TT  1024
#define DD  1024
#define HH  16
#define HDD 64
#define LL  3
#define VV  32000
#define FFD 4096
#define BT  (BB*TT)

// ---------------- static scratch (allocation-free) ----------------
__device__ float g_x   [BT*DD];
__device__ float g_h   [BT*DD];
__device__ float g_qkv [BT*3*DD];
__device__ float g_attn[BT*DD];
__device__ float g_sa  [BT*DD];
__device__ float g_ff1 [(size_t)BT*FFD];
__device__ float g_ff2 [BT*DD];
__device__ float g_wqkv[(size_t)LL*DD*3*DD];
__device__ float g_scores[(size_t)BB*HH*TT*TT];   // 128 MB

// ---------------- embedding ----------------
__global__ void embed_kernel(const int* __restrict__ idx,
                             const float* __restrict__ tok,
                             const float* __restrict__ pos) {
    int bt = blockIdx.x;                 // 0..BT-1
    long long row = (long long)idx[bt];
    int t = bt % TT;
    const float* te = tok + row * DD;
    const float* pe = pos + (long long)t * DD;
    float* xo = g_x + (long long)bt * DD;
    for (int d = threadIdx.x; d < DD; d += blockDim.x)
        xo[d] = te[d] + pe[d];
}

// ---------------- pack wq/wk/wv -> [L][D][3D] (n = m*D + h*HD + k) ----------------
__global__ void pack_kernel(const float* __restrict__ wq,
                            const float* __restrict__ wk,
                            const float* __restrict__ wv) {
    const long long total = (long long)LL * DD * 3 * DD;
    for (long long j = (long long)blockIdx.x * blockDim.x + threadIdx.x;
         j < total; j += (long long)gridDim.x * blockDim.x) {
        int l = (int)(j / ((long long)DD * 3 * DD));
        long long r = j % ((long long)DD * 3 * DD);
        int d = (int)(r / (3 * DD));
        int c = (int)(r % (3 * DD));
        int m = c / DD;
        int c2 = c % DD;
        int h = c2 / HDD;
        int k = c2 % HDD;
        const float* src = (m == 0) ? wq : ((m == 1) ? wk : wv);
        g_wqkv[j] = src[((long long)l * HH + h) * DD * HDD + (long long)d * HDD + k];
    }
}

// ---------------- layernorm (one block per row) ----------------
__global__ void ln_kernel(const float* __restrict__ in,
                          const float* __restrict__ g,
                          const float* __restrict__ b,
                          float* __restrict__ out) {
    int row = blockIdx.x;
    const float* x = in + (long long)row * DD;
    __shared__ float rs[256];
    __shared__ float rs2[256];
    float s = 0.f, s2 = 0.f;
    for (int d = threadIdx.x; d < DD; d += 256) {
        float v = x[d];
        s += v; s2 += v * v;
    }
    rs[threadIdx.x] = s; rs2[threadIdx.x] = s2;
    __syncthreads();
    for (int o = 128; o > 0; o >>= 1) {
        if (threadIdx.x < o) { rs[threadIdx.x] += rs[threadIdx.x + o]; rs2[threadIdx.x] += rs2[threadIdx.x + o]; }
        __syncthreads();
    }
    float mean = rs[0] * (1.0f / DD);
    float var  = rs2[0] * (1.0f / DD) - mean * mean;
    float rstd = rsqrtf(var + 1e-5f);
    float* o = out + (long long)row * DD;
    for (int d = threadIdx.x; d < DD; d += 256)
        o[d] = (x[d] - mean) * rstd * g[d] + b[d];
}

// ---------------- causal scaled softmax over g_scores rows ----------------
__global__ void softmax_kernel() {
    int r = blockIdx.x;            // 0..B*H*T-1
    int t = r % TT;
    float* row = g_scores + (long long)r * TT;
    __shared__ float red[256];
    const float scale = 0.125f;    // HD^-0.5 = 1/8
    float vals[4];
    float mx = -1e30f;
    #pragma unroll
    for (int i = 0; i < 4; i++) {
        int s = threadIdx.x + i * 256;
        float v = (s <= t) ? row[s] * scale : -1e30f;
        vals[i] = v;
        mx = fmaxf(mx, v);
    }
    red[threadIdx.x] = mx; __syncthreads();
    for (int o = 128; o > 0; o >>= 1) {
        if (threadIdx.x < o) red[threadIdx.x] = fmaxf(red[threadIdx.x], red[threadIdx.x + o]);
        __syncthreads();
    }
    float m = red[0];
    __syncthreads();
    float sum = 0.f;
    #pragma unroll
    for (int i = 0; i < 4; i++) {
        float e = expf(vals[i] - m);     // masked entries underflow to 0
        vals[i] = e;
        sum += e;
    }
    red[threadIdx.x] = sum; __syncthreads();
    for (int o = 128; o > 0; o >>= 1) {
        if (threadIdx.x < o) red[threadIdx.x] += red[threadIdx.x + o];
        __syncthreads();
    }
    float inv = 1.0f / red[0];
    #pragma unroll
    for (int i = 0; i < 4; i++) {
        int s = threadIdx.x + i * 256;
        row[s] = vals[i] * inv;
    }
}

// ---------------- elementwise add: x = sa + ff2 ----------------
__global__ void add_kernel() {
    int n = BT * DD;
    for (int i = blockIdx.x * blockDim.x + threadIdx.x; i < n;
         i += gridDim.x * blockDim.x)
        g_x[i] = g_sa[i] + g_ff2[i];
}

// ---------------- generic tiled SIMT GEMM ----------------
// C[M,N] = A[M,K] @ B  (+bias)(+relu).
// A row-major with lda. If !TB, B row-major [K,N] with ldb; if TB, B is memory
// [N,K] row-major with ldb (logical B[k][n] = Bmem[n*ldb+k]).
// Batch: z -> (b = z/HB, h = z%HB); pointer offsets b*Xb + h*Xh.
// EPI: 0 = none, 1 = +bias, 2 = +bias, relu.
template<int BM, int BN, int BK, int TM, int TN, bool TB, int EPI>
__global__ void gemm_kernel(const float* __restrict__ A,
                            const float* __restrict__ B,
                            const float* __restrict__ bias,
                            float* __restrict__ C,
                            int M, int N, int K,
                            int lda, int ldb, int ldc,
                            long long Ab, long long Ah,
                            long long Bb, long long Bh,
                            long long Cb, long long Ch,
                            int HB) {
    constexpr int THREADS = (BM / TM) * (BN / TN);
    __shared__ float As[BK][BM + 4];
    __shared__ float Bs[BK][BN + 4];

    int zb = blockIdx.z / HB;
    int zh = blockIdx.z % HB;
    A += zb * Ab + zh * Ah;
    B += zb * Bb + zh * Bh;
    C += zb * Cb + zh * Ch;

    const int bm = blockIdx.y * BM;
    const int bn = blockIdx.x * BN;
    const int tid = threadIdx.x;
    const int trow = tid / (BN / TN);
    const int tcol = tid % (BN / TN);

    float acc[TM][TN];
    #pragma unroll
    for (int i = 0; i < TM; i++)
        #pragma unroll
        for (int j = 0; j < TN; j++) acc[i][j] = 0.f;

    for (int k0 = 0; k0 < K; k0 += BK) {
        // A tile -> As[k][m]
        #pragma unroll
        for (int i = tid; i < BM * BK; i += THREADS) {
            int r = i / BK, c = i % BK;
            float v = 0.f;
            if (bm + r < M && k0 + c < K)
                v = A[(long long)(bm + r) * lda + (k0 + c)];
            As[c][r] = v;
        }
        // B tile -> Bs[k][n]
        if (!TB) {
            #pragma unroll
            for (int i = tid; i < BK * BN; i += THREADS) {
                int r = i / BN, c = i % BN;
                float v = 0.f;
                if (k0 + r < K && bn + c < N)
                    v = B[(long long)(k0 + r) * ldb + (bn + c)];
                Bs[r][c] = v;
            }
        } else {
            #pragma unroll
            for (int i = tid; i < BN * BK; i += THREADS) {
                int r = i / BK, c = i % BK;
                float v = 0.f;
                if (bn + r < N && k0 + c < K)
                    v = B[(long long)(bn + r) * ldb + (k0 + c)];
                Bs[c][r] = v;
            }
        }
        __syncthreads();

        #pragma unroll
        for (int kk = 0; kk < BK; kk++) {
            float ar[TM], br[TN];
            #pragma unroll
            for (int i = 0; i < TM; i++) ar[i] = As[kk][trow * TM + i];
            #pragma unroll
            for (int j = 0; j < TN; j++) br[j] = Bs[kk][tcol * TN + j];
            #pragma unroll
            for (int i = 0; i < TM; i++)
                #pragma unroll
                for (int j = 0; j < TN; j++)
                    acc[i][j] = fmaf(ar[i], br[j], acc[i][j]);
        }
        __syncthreads();
    }

    #pragma unroll
    for (int i = 0; i < TM; i++) {
        int row = bm + trow * TM + i;
        if (row >= M) continue;
        #pragma unroll
        for (int j = 0; j < TN; j++) {
            int col = bn + tcol * TN + j;
            if (col >= N) continue;
            float v = acc[i][j];
            if (EPI >= 1) v += bias[col];
            if (EPI == 2) v = fmaxf(v, 0.f);
            C[(long long)row * ldc + col] = v;
        }
    }
}

// Convenience launchers
static void gemm128(const float* A, const float* B, const float* bias, float* C,
                    int M, int N, int K, int lda, int ldb, int ldc, int epi) {
    dim3 grid((N + 127) / 128, (M + 127) / 128, 1);
    if (epi == 0)
        gemm_kernel<128,128,8,8,8,false,0><<<grid,256>>>(A,B,bias,C,M,N,K,lda,ldb,ldc,0,0,0,0,0,0,1);
    else if (epi == 1)
        gemm_kernel<128,128,8,8,8,false,1><<<grid,256>>>(A,B,bias,C,M,N,K,lda,ldb,ldc,0,0,0,0,0,0,1);
    else
        gemm_kernel<128,128,8,8,8,false,2><<<grid,256>>>(A,B,bias,C,M,N,K,lda,ldb,ldc,0,0,0,0,0,0,1);
}

extern "C" void kernel_launch(void* const* d_in, const int* in_sizes, int n_in,
                              void* d_out, int out_size) {
    const int*   idx         = (const int*)d_in[0];     // int32 (JAX x64 disabled)
    const float* tok_emb     = (const float*)d_in[1];
    const float* pos_emb     = (const float*)d_in[2];
    const float* wq          = (const float*)d_in[3];
    const float* wk          = (const float*)d_in[4];
    const float* wv          = (const float*)d_in[5];
    const float* w_proj      = (const float*)d_in[6];
    const float* b_proj      = (const float*)d_in[7];
    const float* w1          = (const float*)d_in[8];
    const float* b1          = (const float*)d_in[9];
    const float* w2          = (const float*)d_in[10];
    const float* b2          = (const float*)d_in[11];
    const float* ln1_g       = (const float*)d_in[12];
    const float* ln1_b       = (const float*)d_in[13];
    const float* ln2_g       = (const float*)d_in[14];
    const float* ln2_b       = (const float*)d_in[15];
    const float* lnf_g       = (const float*)d_in[16];
    const float* lnf_b       = (const float*)d_in[17];
    const float* w_lm        = (const float*)d_in[18];
    const float* b_lm        = (const float*)d_in[19];
    float* out = (float*)d_out;

    float *px, *ph, *pqkv, *pattn, *psa, *pff1, *pff2, *pwqkv, *pscores;
    cudaGetSymbolAddress((void**)&px,     g_x);
    cudaGetSymbolAddress((void**)&ph,     g_h);
    cudaGetSymbolAddress((void**)&pqkv,   g_qkv);
    cudaGetSymbolAddress((void**)&pattn,  g_attn);
    cudaGetSymbolAddress((void**)&psa,    g_sa);
    cudaGetSymbolAddress((void**)&pff1,   g_ff1);
    cudaGetSymbolAddress((void**)&pff2,   g_ff2);
    cudaGetSymbolAddress((void**)&pwqkv,  g_wqkv);
    cudaGetSymbolAddress((void**)&pscores,g_scores);

    // pack QKV weights, compute embeddings
    pack_kernel<<<4096, 256>>>(wq, wk, wv);
    embed_kernel<<<BT, 256>>>(idx, tok_emb, pos_emb);

    const long long TT2 = (long long)TT * TT;

    for (int l = 0; l < LL; l++) {
        // ln1(x) -> h
        ln_kernel<<<BT, 256>>>(px, ln1_g + (long long)l*DD, ln1_b + (long long)l*DD, ph);

        // fused QKV: h[2048,1024] @ wqkv_l[1024,3072] -> qkv
        gemm128(ph, pwqkv + (long long)l*DD*3*DD, nullptr, pqkv,
                BT, 3*DD, DD, DD, 3*DD, 3*DD, 0);

        // scores = Q @ K^T  (batched over B*H)
        {
            dim3 grid(TT/128, TT/128, BB*HH);
            gemm_kernel<128,128,8,8,8,true,0><<<grid,256>>>(
                pqkv,            // Q section
                pqkv + DD,       // K section
                nullptr, pscores,
                TT, TT, HDD,
                3*DD, 3*DD, TT,
                (long long)TT*3*DD, HDD,      // A: per-b, per-h
                (long long)TT*3*DD, HDD,      // B
                (long long)HH*TT2, TT2,       // C
                HH);
        }

        // causal softmax (in place, scale 1/8)
        softmax_kernel<<<BB*HH*TT, 256>>>();

        // attn = P @ V  (batched), written as [b,t,h*HD]
        {
            dim3 grid(1, TT/64, BB*HH);
            gemm_kernel<64,64,16,4,4,false,0><<<grid,256>>>(
                pscores,
                pqkv + 2*DD,     // V section
                nullptr, pattn,
                TT, HDD, TT,
                TT, 3*DD, DD,
                (long long)HH*TT2, TT2,
                (long long)TT*3*DD, HDD,
                (long long)TT*DD, HDD,
                HH);
        }

        // sa = attn @ w_proj + b_proj
        gemm128(pattn, w_proj + (long long)l*DD*DD, b_proj + (long long)l*DD, psa,
                BT, DD, DD, DD, DD, DD, 1);

        // ln2(x) -> h
        ln_kernel<<<BT, 256>>>(px, ln2_g + (long long)l*DD, ln2_b + (long long)l*DD, ph);

        // ff1 = relu(h @ w1 + b1)
        gemm128(ph, w1 + (long long)l*DD*FFD, b1 + (long long)l*FFD, pff1,
                BT, FFD, DD, DD, FFD, FFD, 2);

        // ff2 = ff1 @ w2 + b2
        gemm128(pff1, w2 + (long long)l*FFD*DD, b2 + (long long)l*DD, pff2,
                BT, DD, FFD, FFD, DD, DD, 1);

        // x = sa + ff2   (no residual, faithful to source)
        add_kernel<<<2048, 256>>>();
    }

    // final layernorm
    ln_kernel<<<BT, 256>>>(px, lnf_g, lnf_b, ph);

    // logits = h @ w_lm + b_lm  -> d_out [B,T,V]
    gemm128(ph, w_lm, b_lm, out, BT, VV, DD, DD, VV, VV, 1);
}

// round 4
// speedup vs baseline: 8.8335x; 8.8335x over previous
#include <cuda_runtime.h>
#include <math.h>

// Problem constants
#define BB  2
#define TT  1024
#define DD  1024
#define HH  16
#define HDD 64
#define LL  3
#define VV  32000
#define FFD 4096
#define BT  (BB*TT)

#define BM 128
#define BN 128
#define BK 16

// ---------------- static scratch (allocation-free) ----------------
__device__ float g_x   [BT*DD];
__device__ float g_h   [BT*DD];
__device__ float g_qkv [BT*3*DD];
__device__ float g_attn[BT*DD];
__device__ float g_sa  [BT*DD];
__device__ float g_ff1 [(size_t)BT*FFD];
__device__ float g_ff2 [BT*DD];
__device__ float g_wqkv[(size_t)LL*DD*3*DD];
__device__ float g_scores[(size_t)BB*HH*TT*TT];   // 128 MB

// ---------------- helpers ----------------
__device__ __forceinline__ unsigned f2tf32(float x) {
    unsigned r;
    asm("cvt.rna.tf32.f32 %0, %1;" : "=r"(r) : "f"(x));
    return r;
}

__device__ __forceinline__ void mma_tf32(float* c, const unsigned* a, const unsigned* b) {
    asm volatile(
        "mma.sync.aligned.m16n8k8.row.col.f32.tf32.tf32.f32 "
        "{%0,%1,%2,%3},{%4,%5,%6,%7},{%8,%9},{%0,%1,%2,%3};"
        : "+f"(c[0]), "+f"(c[1]), "+f"(c[2]), "+f"(c[3])
        : "r"(a[0]), "r"(a[1]), "r"(a[2]), "r"(a[3]), "r"(b[0]), "r"(b[1]));
}

// ---------------- embedding ----------------
__global__ void embed_kernel(const int* __restrict__ idx,
                             const float* __restrict__ tok,
                             const float* __restrict__ pos) {
    int bt = blockIdx.x;
    long long row = (long long)idx[bt];
    int t = bt % TT;
    const float* te = tok + row * DD;
    const float* pe = pos + (long long)t * DD;
    float* xo = g_x + (long long)bt * DD;
    for (int d = threadIdx.x; d < DD; d += blockDim.x)
        xo[d] = te[d] + pe[d];
}

// ---------------- pack wq/wk/wv -> [L][D][3D] ----------------
__global__ void pack_kernel(const float* __restrict__ wq,
                            const float* __restrict__ wk,
                            const float* __restrict__ wv) {
    const long long total = (long long)LL * DD * 3 * DD;
    for (long long j = (long long)blockIdx.x * blockDim.x + threadIdx.x;
         j < total; j += (long long)gridDim.x * blockDim.x) {
        int l = (int)(j / ((long long)DD * 3 * DD));
        long long r = j % ((long long)DD * 3 * DD);
        int d = (int)(r / (3 * DD));
        int c = (int)(r % (3 * DD));
        int m = c / DD;
        int c2 = c % DD;
        int h = c2 / HDD;
        int k = c2 % HDD;
        const float* src = (m == 0) ? wq : ((m == 1) ? wk : wv);
        g_wqkv[j] = src[((long long)l * HH + h) * DD * HDD + (long long)d * HDD + k];
    }
}

// ---------------- layernorm ----------------
__global__ void ln_kernel(const float* __restrict__ in,
                          const float* __restrict__ g,
                          const float* __restrict__ b,
                          float* __restrict__ out) {
    int row = blockIdx.x;
    const float* x = in + (long long)row * DD;
    __shared__ float rs[256];
    __shared__ float rs2[256];
    float s = 0.f, s2 = 0.f;
    for (int d = threadIdx.x; d < DD; d += 256) {
        float v = x[d];
        s += v; s2 += v * v;
    }
    rs[threadIdx.x] = s; rs2[threadIdx.x] = s2;
    __syncthreads();
    for (int o = 128; o > 0; o >>= 1) {
        if (threadIdx.x < o) { rs[threadIdx.x] += rs[threadIdx.x + o]; rs2[threadIdx.x] += rs2[threadIdx.x + o]; }
        __syncthreads();
    }
    float mean = rs[0] * (1.0f / DD);
    float var  = rs2[0] * (1.0f / DD) - mean * mean;
    float rstd = rsqrtf(var + 1e-5f);
    float* o = out + (long long)row * DD;
    for (int d = threadIdx.x; d < DD; d += 256)
        o[d] = (x[d] - mean) * rstd * g[d] + b[d];
}

// ---------------- causal scaled softmax ----------------
__global__ void softmax_kernel() {
    int r = blockIdx.x;
    int t = r % TT;
    float* row = g_scores + (long long)r * TT;
    __shared__ float red[256];
    const float scale = 0.125f;
    float vals[4];
    float mx = -1e30f;
    #pragma unroll
    for (int i = 0; i < 4; i++) {
        int s = threadIdx.x + i * 256;
        float v = (s <= t) ? row[s] * scale : -1e30f;
        vals[i] = v;
        mx = fmaxf(mx, v);
    }
    red[threadIdx.x] = mx; __syncthreads();
    for (int o = 128; o > 0; o >>= 1) {
        if (threadIdx.x < o) red[threadIdx.x] = fmaxf(red[threadIdx.x], red[threadIdx.x + o]);
        __syncthreads();
    }
    float m = red[0];
    __syncthreads();
    float sum = 0.f;
    #pragma unroll
    for (int i = 0; i < 4; i++) {
        float e = expf(vals[i] - m);
        vals[i] = e;
        sum += e;
    }
    red[threadIdx.x] = sum; __syncthreads();
    for (int o = 128; o > 0; o >>= 1) {
        if (threadIdx.x < o) red[threadIdx.x] += red[threadIdx.x + o];
        __syncthreads();
    }
    float inv = 1.0f / red[0];
    #pragma unroll
    for (int i = 0; i < 4; i++) {
        int s = threadIdx.x + i * 256;
        row[s] = vals[i] * inv;
    }
}

// ---------------- elementwise add: x = sa + ff2 ----------------
__global__ void add_kernel() {
    int n = BT * DD;
    for (int i = blockIdx.x * blockDim.x + threadIdx.x; i < n;
         i += gridDim.x * blockDim.x)
        g_x[i] = g_sa[i] + g_ff2[i];
}

// ---------------- tf32 tensor-core GEMM ----------------
// C[M,N] = A[M,K] @ B (+bias)(+relu).
// A row-major (lda). If !TB: B row-major [K,N] (ldb). If TB: B memory [N,K]
// row-major (ldb), logical B[k][n] = Bmem[n*ldb+k].
// Batched via blockIdx.z -> (zb, zh) with pointer offsets.
// EPI: 0 none, 1 +bias, 2 +bias+relu.
// CSKIP: skip tiles strictly above causal diagonal (scores).
// CCLIP: clip K loop to bm+BM (PV with causal-zero probabilities).
// Requires: M % 128 == 0, K % 16 == 0; N arbitrary (guarded); if TB, N % 128 == 0.
template<int EPI, bool TB, bool CSKIP, bool CCLIP>
__global__ void __launch_bounds__(256)
mma_gemm(const float* __restrict__ A, const float* __restrict__ B,
         const float* __restrict__ bias, float* __restrict__ C,
         int M, int N, int K, int lda, int ldb, int ldc,
         long long Ab, long long Ah, long long Bb, long long Bh,
         long long Cb, long long Ch, int HB) {
    __shared__ __align__(16) unsigned As[2][BM][BK + 4];   // [m][k], pad->20
    __shared__ __align__(16) unsigned Bs[2][BK][BN + 8];   // [k][n], pad->136

    const int zb = blockIdx.z / HB;
    const int zh = blockIdx.z % HB;
    A += zb * Ab + zh * Ah;
    B += zb * Bb + zh * Bh;
    C += zb * Cb + zh * Ch;

    const int bm = blockIdx.x * BM;
    const int bn = blockIdx.y * BN;
    if (CSKIP && bn >= bm + BM) return;   // fully masked causal tile

    const int Kend = CCLIP ? min(K, bm + BM) : K;
    const int nIter = Kend >> 4;

    const int tid  = threadIdx.x;
    const int warp = tid >> 5;
    const int lane = tid & 31;
    const int g    = lane >> 2;
    const int tig  = lane & 3;
    const int wm   = (warp & 3) * 32;
    const int wn   = (warp >> 2) * 64;

    float acc[2][8][4];
    #pragma unroll
    for (int i = 0; i < 2; i++)
        #pragma unroll
        for (int j = 0; j < 8; j++)
            #pragma unroll
            for (int q = 0; q < 4; q++) acc[i][j][q] = 0.f;

    // staging register buffers
    float4 ra[2], rb[2];

    // A: thread covers row = p*64 + tid/4, col4 = (tid%4)*4
    const int a_r = tid >> 2;
    const int a_c = (tid & 3) << 2;
    // B (!TB): row = p*8 + tid/32, col4 = (tid%32)*4
    const int b_r = tid >> 5;
    const int b_c = (tid & 31) << 2;
    // B (TB): n = p*64 + tid/4, k4 = (tid%4)*4
    const int t_n = tid >> 2;
    const int t_k = (tid & 3) << 2;

    auto loadA = [&](int k0) {
        #pragma unroll
        for (int p = 0; p < 2; p++) {
            int r = p * 64 + a_r;
            ra[p] = *reinterpret_cast<const float4*>(A + (long long)(bm + r) * lda + (k0 + a_c));
        }
    };
    auto loadB = [&](int k0) {
        if (!TB) {
            #pragma unroll
            for (int p = 0; p < 2; p++) {
                int r = k0 + p * 8 + b_r;
                int c = bn + b_c;
                if (c < N)
                    rb[p] = *reinterpret_cast<const float4*>(B + (long long)r * ldb + c);
                else
                    rb[p] = make_float4(0.f, 0.f, 0.f, 0.f);
            }
        } else {
            #pragma unroll
            for (int p = 0; p < 2; p++) {
                int n = bn + p * 64 + t_n;
                rb[p] = *reinterpret_cast<const float4*>(B + (long long)n * ldb + (k0 + t_k));
            }
        }
    };
    auto storeAB = [&](int buf) {
        #pragma unroll
        for (int p = 0; p < 2; p++) {
            int r = p * 64 + a_r;
            uint4 v = make_uint4(f2tf32(ra[p].x), f2tf32(ra[p].y), f2tf32(ra[p].z), f2tf32(ra[p].w));
            *reinterpret_cast<uint4*>(&As[buf][r][a_c]) = v;
        }
        if (!TB) {
            #pragma unroll
            for (int p = 0; p < 2; p++) {
                int r = p * 8 + b_r;
                uint4 v = make_uint4(f2tf32(rb[p].x), f2tf32(rb[p].y), f2tf32(rb[p].z), f2tf32(rb[p].w));
                *reinterpret_cast<uint4*>(&Bs[buf][r][b_c]) = v;
            }
        } else {
            #pragma unroll
            for (int p = 0; p < 2; p++) {
                int n = p * 64 + t_n;
                Bs[buf][t_k + 0][n] = f2tf32(rb[p].x);
                Bs[buf][t_k + 1][n] = f2tf32(rb[p].y);
                Bs[buf][t_k + 2][n] = f2tf32(rb[p].z);
                Bs[buf][t_k + 3][n] = f2tf32(rb[p].w);
            }
        }
    };
    auto compute = [&](int buf) {
        #pragma unroll
        for (int ks = 0; ks < 2; ks++) {
            const int kk = ks * 8;
            unsigned af[2][4], bf[8][2];
            #pragma unroll
            for (int mi = 0; mi < 2; mi++) {
                int r0 = wm + mi * 16;
                // PTX m16n8k8.tf32 A fragment: a0=(g,t) a1=(g+8,t) a2=(g,t+4) a3=(g+8,t+4)
                af[mi][0] = As[buf][r0 + g][kk + tig];
                af[mi][1] = As[buf][r0 + g + 8][kk + tig];
                af[mi][2] = As[buf][r0 + g][kk + tig + 4];
                af[mi][3] = As[buf][r0 + g + 8][kk + tig + 4];
            }
            #pragma unroll
            for (int nj = 0; nj < 8; nj++) {
                int c0 = wn + nj * 8 + g;
                bf[nj][0] = Bs[buf][kk + tig][c0];
                bf[nj][1] = Bs[buf][kk + tig + 4][c0];
            }
            #pragma unroll
            for (int mi = 0; mi < 2; mi++)
                #pragma unroll
                for (int nj = 0; nj < 8; nj++)
                    mma_tf32(acc[mi][nj], af[mi], bf[nj]);
        }
    };

    loadA(0); loadB(0);
    storeAB(0);
    __syncthreads();

    for (int it = 0; it < nIter; it++) {
        int buf = it & 1;
        bool more = (it + 1 < nIter);
        if (more) { loadA((it + 1) << 4); loadB((it + 1) << 4); }
        compute(buf);
        if (more) storeAB(buf ^ 1);
        __syncthreads();
    }

    // epilogue: c0:(r,c) c1:(r,c+1) c2:(r+8,c) c3:(r+8,c+1)
    #pragma unroll
    for (int mi = 0; mi < 2; mi++) {
        int row = bm + wm + mi * 16 + g;
        #pragma unroll
        for (int nj = 0; nj < 8; nj++) {
            int col = bn + wn + nj * 8 + tig * 2;
            if (col >= N) continue;
            float v0 = acc[mi][nj][0];
            float v1 = acc[mi][nj][1];
            float v2 = acc[mi][nj][2];
            float v3 = acc[mi][nj][3];
            if (EPI >= 1) {
                float bb0 = bias[col];
                float bb1 = bias[col + 1];
                v0 += bb0; v1 += bb1; v2 += bb0; v3 += bb1;
            }
            if (EPI == 2) {
                v0 = fmaxf(v0, 0.f); v1 = fmaxf(v1, 0.f);
                v2 = fmaxf(v2, 0.f); v3 = fmaxf(v3, 0.f);
            }
            C[(long long)row * ldc + col]           = v0;
            C[(long long)row * ldc + col + 1]       = v1;
            C[(long long)(row + 8) * ldc + col]     = v2;
            C[(long long)(row + 8) * ldc + col + 1] = v3;
        }
    }
}

// dense launcher (non-batched)
static void dense_gemm(const float* A, const float* B, const float* bias, float* C,
                       int M, int N, int K, int lda, int ldb, int ldc, int epi) {
    dim3 grid(M / BM, (N + BN - 1) / BN, 1);
    if (epi == 0)
        mma_gemm<0,false,false,false><<<grid,256>>>(A,B,bias,C,M,N,K,lda,ldb,ldc,0,0,0,0,0,0,1);
    else if (epi == 1)
        mma_gemm<1,false,false,false><<<grid,256>>>(A,B,bias,C,M,N,K,lda,ldb,ldc,0,0,0,0,0,0,1);
    else
        mma_gemm<2,false,false,false><<<grid,256>>>(A,B,bias,C,M,N,K,lda,ldb,ldc,0,0,0,0,0,0,1);
}

extern "C" void kernel_launch(void* const* d_in, const int* in_sizes, int n_in,
                              void* d_out, int out_size) {
    const int*   idx         = (const int*)d_in[0];     // int32
    const float* tok_emb     = (const float*)d_in[1];
    const float* pos_emb     = (const float*)d_in[2];
    const float* wq          = (const float*)d_in[3];
    const float* wk          = (const float*)d_in[4];
    const float* wv          = (const float*)d_in[5];
    const float* w_proj      = (const float*)d_in[6];
    const float* b_proj      = (const float*)d_in[7];
    const float* w1          = (const float*)d_in[8];
    const float* b1          = (const float*)d_in[9];
    const float* w2          = (const float*)d_in[10];
    const float* b2          = (const float*)d_in[11];
    const float* ln1_g       = (const float*)d_in[12];
    const float* ln1_b       = (const float*)d_in[13];
    const float* ln2_g       = (const float*)d_in[14];
    const float* ln2_b       = (const float*)d_in[15];
    const float* lnf_g       = (const float*)d_in[16];
    const float* lnf_b       = (const float*)d_in[17];
    const float* w_lm        = (const float*)d_in[18];
    const float* b_lm        = (const float*)d_in[19];
    float* out = (float*)d_out;

    float *px, *ph, *pqkv, *pattn, *psa, *pff1, *pff2, *pwqkv, *pscores;
    cudaGetSymbolAddress((void**)&px,     g_x);
    cudaGetSymbolAddress((void**)&ph,     g_h);
    cudaGetSymbolAddress((void**)&pqkv,   g_qkv);
    cudaGetSymbolAddress((void**)&pattn,  g_attn);
    cudaGetSymbolAddress((void**)&psa,    g_sa);
    cudaGetSymbolAddress((void**)&pff1,   g_ff1);
    cudaGetSymbolAddress((void**)&pff2,   g_ff2);
    cudaGetSymbolAddress((void**)&pwqkv,  g_wqkv);
    cudaGetSymbolAddress((void**)&pscores,g_scores);

    pack_kernel<<<4096, 256>>>(wq, wk, wv);
    embed_kernel<<<BT, 256>>>(idx, tok_emb, pos_emb);

    const long long TT2 = (long long)TT * TT;

    for (int l = 0; l < LL; l++) {
        ln_kernel<<<BT, 256>>>(px, ln1_g + (long long)l*DD, ln1_b + (long long)l*DD, ph);

        // fused QKV
        dense_gemm(ph, pwqkv + (long long)l*DD*3*DD, nullptr, pqkv,
                   BT, 3*DD, DD, DD, 3*DD, 3*DD, 0);

        // scores = Q @ K^T, batched over B*H, causal tiles skipped
        {
            dim3 grid(TT/BM, TT/BN, BB*HH);
            mma_gemm<0,true,true,false><<<grid,256>>>(
                pqkv,              // Q
                pqkv + DD,         // K (memory [t,k] -> TB)
                nullptr, pscores,
                TT, TT, HDD,
                3*DD, 3*DD, TT,
                (long long)TT*3*DD, HDD,
                (long long)TT*3*DD, HDD,
                (long long)HH*TT2, TT2,
                HH);
        }

        softmax_kernel<<<BB*HH*TT, 256>>>();

        // attn = P @ V, batched, K clipped to causal extent
        {
            dim3 grid(TT/BM, 1, BB*HH);
            mma_gemm<0,false,false,true><<<grid,256>>>(
                pscores,
                pqkv + 2*DD,       // V
                nullptr, pattn,
                TT, HDD, TT,
                TT, 3*DD, DD,
                (long long)HH*TT2, TT2,
                (long long)TT*3*DD, HDD,
                (long long)TT*DD, HDD,
                HH);
        }

        // sa = attn @ w_proj + b_proj
        dense_gemm(pattn, w_proj + (long long)l*DD*DD, b_proj + (long long)l*DD, psa,
                   BT, DD, DD, DD, DD, DD, 1);

        ln_kernel<<<BT, 256>>>(px, ln2_g + (long long)l*DD, ln2_b + (long long)l*DD, ph);

        // ff1 = relu(h @ w1 + b1)
        dense_gemm(ph, w1 + (long long)l*DD*FFD, b1 + (long long)l*FFD, pff1,
                   BT, FFD, DD, DD, FFD, FFD, 2);

        // ff2 = ff1 @ w2 + b2
        dense_gemm(pff1, w2 + (long long)l*FFD*DD, b2 + (long long)l*DD, pff2,
                   BT, DD, FFD, FFD, DD, DD, 1);

        add_kernel<<<2048, 256>>>();
    }

    ln_kernel<<<BT, 256>>>(px, lnf_g, lnf_b, ph);

    // logits = h @ w_lm + b_lm
    dense_gemm(ph, w_lm, b_lm, out, BT, VV, DD, DD, VV, VV, 1);
}